// round 6
// baseline (speedup 1.0000x reference)
#include <cuda_runtime.h>

// ---------------------------------------------------------------------------
// signalEncoding: B=256, S=512, SF=4, NSIG=50
// Kernel A (prep): x -> sharedCNN(sharedCNN(x)) + x -> LayerNorm -> scratch d
// Kernel B (sig):  per-signal stack with FUSED linear conv pairs:
//   L12 = conv2(k5) o conv1(k7)  -> single 4->4 k11 conv, then SELU
//   L34 = conv4(k5,d2) o conv3(k5) -> single 4->1 k13 conv, then SELU
// Reflect boundaries handled exactly via explicit H1/H3 edge values.
// Batch packed 2-wide into f32x2. All intermediates in SMEM.
// ---------------------------------------------------------------------------

#define NPOS 512
#define HALO 4
#define CST  528           // per-channel smem stride (float2), 528 % 16 == 0
#define NBP  128           // batch pairs

__device__ __forceinline__ int sidx(int c, int p) {
    int q = p + HALO;                    // q in [-? .. 519], valid q >= 0
    return c * CST + (q ^ ((q >> 4) & 3));
}

__device__ __forceinline__ int refl(int q) {
    q = q < 0 ? -q : q;
    return q > 511 ? 1022 - q : q;
}

union F2U { float2 f; unsigned long long u; };

__device__ __forceinline__ float2 ffma2(float2 a, float2 b, float2 c) {
    F2U ua, ub, uc, ud;
    ua.f = a; ub.f = b; uc.f = c;
    asm("fma.rn.f32x2 %0, %1, %2, %3;" : "=l"(ud.u) : "l"(ua.u), "l"(ub.u), "l"(uc.u));
    return ud.f;
}

__device__ __forceinline__ float2 splat(float w) { return make_float2(w, w); }

__device__ __forceinline__ float2 add2(float2 a, float2 b) {
    return make_float2(a.x + b.x, a.y + b.y);
}

__device__ __forceinline__ float selu_s(float x) {
    const float SC = 1.0507009873554805f;
    const float SA = 1.7580993408473766f;
    return x > 0.f ? SC * x : SA * expm1f(x);
}
__device__ __forceinline__ float2 selu2(float2 v) {
    return make_float2(selu_s(v.x), selu_s(v.y));
}

// reflect halo: buf[-i] = buf[i], buf[511+i] = buf[511-i], i=1..4
__device__ __forceinline__ void fill_halo(float2* buf, int C, int tid) {
    if (tid < C * 8) {
        int c = tid >> 3, k = tid & 7;
        if (k < 4) { int i = k + 1; buf[sidx(c, -i)]      = buf[sidx(c, i)]; }
        else       { int i = k - 3; buf[sidx(c, 511 + i)] = buf[sidx(c, 511 - i)]; }
    }
}

// scratch: normalized d, float2 over batch pair: [(bp*4 + c)*512 + p]
__device__ float2 g_D[NBP * 4 * NPOS];

// ---------------------------------------------------------------------------
// Kernel A: prep.  grid=128 (batch pair), block=512. (unchanged from R5 pass)
// ---------------------------------------------------------------------------

__device__ __forceinline__ void shared_conv1(const float2* S, float2* Dst,
                                             const float* w1, const float* b1, int t) {
    #pragma unroll
    for (int o = 0; o < 8; o++) {
        float2 acc = splat(b1[o]);
        #pragma unroll
        for (int c = 0; c < 4; c++)
            #pragma unroll
            for (int j = 0; j < 5; j++) {
                float w = w1[o * 20 + c * 5 + j];
                acc = ffma2(splat(w), S[sidx(c, t - 2 + j)], acc);
            }
        Dst[sidx(o, t)] = selu2(acc);
    }
}

__device__ __forceinline__ void shared_conv2(const float2* S, const float* w2,
                                             const float* b2, int t, float2 out[4]) {
    #pragma unroll
    for (int o = 0; o < 4; o++) {
        float2 acc = splat(b2[o]);
        #pragma unroll
        for (int c = 0; c < 8; c++)
            #pragma unroll
            for (int j = 0; j < 5; j++) {
                float w = w2[o * 40 + c * 5 + j];
                acc = ffma2(splat(w), S[sidx(c, t - 4 + 2 * j)], acc);
            }
        out[o] = acc;
    }
}

extern "C" __global__ void __launch_bounds__(512)
prep_kernel(const float* __restrict__ lat,
            const float* __restrict__ sw1, const float* __restrict__ sb1,
            const float* __restrict__ sw2, const float* __restrict__ sb2,
            const float* __restrict__ lng, const float* __restrict__ lnb) {
    extern __shared__ unsigned char sm[];
    float2* X   = (float2*)sm;            // 4 * CST
    float2* A   = X + 4 * CST;            // 8 * CST
    float2* Bu  = A + 8 * CST;            // 4 * CST
    float*  W   = (float*)(Bu + 4 * CST); // 336 floats
    float2* RED = (float2*)(W + 336);     // 64 float2

    const int t  = threadIdx.x;
    const int bp = blockIdx.x;
    const int lane = t & 31, wid = t >> 5;

    if (t < 332) {
        float v;
        if      (t < 160) v = sw1[t];
        else if (t < 168) v = sb1[t - 160];
        else if (t < 328) v = sw2[t - 168];
        else              v = sb2[t - 328];
        W[t] = v;
    }
    const float* w1 = W, * b1 = W + 160, * w2 = W + 168, * b2 = W + 328;

    float4 v0 = reinterpret_cast<const float4*>(lat + (size_t)(2 * bp)     * 2048)[t];
    float4 v1 = reinterpret_cast<const float4*>(lat + (size_t)(2 * bp + 1) * 2048)[t];
    X[sidx(0, t)] = make_float2(v0.x, v1.x);
    X[sidx(1, t)] = make_float2(v0.y, v1.y);
    X[sidx(2, t)] = make_float2(v0.z, v1.z);
    X[sidx(3, t)] = make_float2(v0.w, v1.w);
    __syncthreads();
    fill_halo(X, 4, t);
    __syncthreads();

    shared_conv1(X, A, w1, b1, t);
    __syncthreads(); fill_halo(A, 8, t); __syncthreads();
    {
        float2 tmp[4];
        shared_conv2(A, w2, b2, t, tmp);
        __syncthreads();
        #pragma unroll
        for (int c = 0; c < 4; c++) Bu[sidx(c, t)] = tmp[c];
    }
    __syncthreads(); fill_halo(Bu, 4, t); __syncthreads();

    shared_conv1(Bu, A, w1, b1, t);
    __syncthreads(); fill_halo(A, 8, t); __syncthreads();
    float2 dv[4];
    {
        float2 cc[4];
        shared_conv2(A, w2, b2, t, cc);
        #pragma unroll
        for (int c = 0; c < 4; c++) dv[c] = add2(cc[c], X[sidx(c, t)]);
    }

    float2 mean[4], var[4];
    {
        float2 sv[4];
        #pragma unroll
        for (int c = 0; c < 4; c++) sv[c] = dv[c];
        #pragma unroll
        for (int c = 0; c < 4; c++)
            for (int off = 16; off; off >>= 1) {
                sv[c].x += __shfl_xor_sync(0xffffffffu, sv[c].x, off);
                sv[c].y += __shfl_xor_sync(0xffffffffu, sv[c].y, off);
            }
        if (lane == 0)
            #pragma unroll
            for (int c = 0; c < 4; c++) RED[c * 16 + wid] = sv[c];
        __syncthreads();
        if (t < 32) {
            #pragma unroll
            for (int c = 0; c < 4; c++) {
                float2 v = (lane < 16) ? RED[c * 16 + lane] : make_float2(0.f, 0.f);
                for (int off = 8; off; off >>= 1) {
                    v.x += __shfl_xor_sync(0xffffffffu, v.x, off);
                    v.y += __shfl_xor_sync(0xffffffffu, v.y, off);
                }
                if (lane == 0) RED[c * 16] = v;
            }
        }
        __syncthreads();
        const float inv = 1.0f / 512.0f;
        #pragma unroll
        for (int c = 0; c < 4; c++) {
            float2 s = RED[c * 16];
            mean[c] = make_float2(s.x * inv, s.y * inv);
        }
        __syncthreads();
    }
    {
        float2 sv[4];
        #pragma unroll
        for (int c = 0; c < 4; c++) {
            float dx = dv[c].x - mean[c].x, dy = dv[c].y - mean[c].y;
            sv[c] = make_float2(dx * dx, dy * dy);
        }
        #pragma unroll
        for (int c = 0; c < 4; c++)
            for (int off = 16; off; off >>= 1) {
                sv[c].x += __shfl_xor_sync(0xffffffffu, sv[c].x, off);
                sv[c].y += __shfl_xor_sync(0xffffffffu, sv[c].y, off);
            }
        if (lane == 0)
            #pragma unroll
            for (int c = 0; c < 4; c++) RED[c * 16 + wid] = sv[c];
        __syncthreads();
        if (t < 32) {
            #pragma unroll
            for (int c = 0; c < 4; c++) {
                float2 v = (lane < 16) ? RED[c * 16 + lane] : make_float2(0.f, 0.f);
                for (int off = 8; off; off >>= 1) {
                    v.x += __shfl_xor_sync(0xffffffffu, v.x, off);
                    v.y += __shfl_xor_sync(0xffffffffu, v.y, off);
                }
                if (lane == 0) RED[c * 16] = v;
            }
        }
        __syncthreads();
        const float inv = 1.0f / 512.0f;
        #pragma unroll
        for (int c = 0; c < 4; c++) {
            float2 s = RED[c * 16];
            var[c] = make_float2(s.x * inv, s.y * inv);
        }
    }

    const float EPS = 1e-10f;
    float g = lng[t], bb = lnb[t];
    #pragma unroll
    for (int c = 0; c < 4; c++) {
        float rx = 1.0f / sqrtf(var[c].x + EPS);
        float ry = 1.0f / sqrtf(var[c].y + EPS);
        float2 dn;
        dn.x = (dv[c].x - mean[c].x) * rx * g + bb;
        dn.y = (dv[c].y - mean[c].y) * ry * g + bb;
        g_D[(size_t)(bp * 4 + c) * NPOS + t] = dn;
    }
}

// ---------------------------------------------------------------------------
// Kernel B: fused per-signal stacks. grid=(128 bpair, 25 siggroups), block=128,
// 4 contiguous positions per thread, 2 signals per CTA.
//
// W float layout:
//   [0..175]   Weff12[o*44 + c*11 + t]   (4->4, k11 composed)
//   [176..179] beff12[o]
//   [180..339] w2raw[o*40 + m*5 + j2]
//   [340..343] b2raw[o]
//   [344..395] Weff34[c*13 + t]          (4->1, k13 composed)
//   [396]      beff34
//   [397..436] w3raw[m*20 + c*5 + j3]
//   [437..438] b3raw[m]
//   [439..448] w4raw[m*5 + j4]
//   [449]      b4raw
// ---------------------------------------------------------------------------

extern "C" __global__ void __launch_bounds__(128, 5)
sig_kernel(const float* __restrict__ sw1, const float* __restrict__ sb1,
           const float* __restrict__ sw2, const float* __restrict__ sb2,
           const float* __restrict__ sw3, const float* __restrict__ sb3,
           const float* __restrict__ sw4, const float* __restrict__ sb4,
           float* __restrict__ out) {
    extern __shared__ unsigned char sm[];
    float2* D   = (float2*)sm;            // 4 * CST
    float2* H2  = D + 4 * CST;            // 4 * CST
    float2* He  = H2 + 4 * CST;           // 64  (H1 edges: [m*8 + k], k<4: q=k, k>=4: q=508+(k-4))
    float2* H3e = He + 64;                // 32  (H3 edges: [m*16 + k], k<8: q=k, k>=8: q=504+(k-8))
    float*  W   = (float*)(H3e + 32);     // 450 floats

    const int tid  = threadIdx.x;
    const int bp   = blockIdx.x;
    const int base = tid * 4;

    // load d for this batch pair
    {
        const float2* gd = g_D + (size_t)bp * 4 * NPOS;
        for (int i = tid; i < 4 * NPOS; i += 128) {
            int c = i >> 9, p = i & 511;
            D[sidx(c, p)] = gd[i];
        }
    }
    __syncthreads();
    fill_halo(D, 4, tid);

    for (int sl = 0; sl < 2; sl++) {
        const int sig = blockIdx.y * 2 + sl;
        __syncthreads();   // prev signal fully consumed W/He/H3e/H2 (and D halo on sl=0)

        // ---- stage: composed weights + H1 edge values + raw weights ----
        for (int i = tid; i < 514; i += 128) {
            if (i < 176) {
                // Weff12[o][c][t] = sum_m sum_j2 w2[o][m][j2] * w1[m][c][t-j2]
                int o = i / 44, rem = i % 44, c = rem / 11, t = rem % 11;
                const float* w2p = sw2 + sig * 160 + o * 40;
                const float* w1p = sw1 + sig * 224;
                float s = 0.f;
                #pragma unroll
                for (int m = 0; m < 8; m++)
                    #pragma unroll
                    for (int j2 = 0; j2 < 5; j2++) {
                        int j1 = t - j2;
                        if (j1 >= 0 && j1 <= 6)
                            s += w2p[m * 5 + j2] * w1p[m * 28 + c * 7 + j1];
                    }
                W[i] = s;
            } else if (i < 240) {
                // He: true H1 values at edge positions (from D, reflect halo 4 ok)
                int k = i - 176, m = k >> 3, kk = k & 7;
                int q = kk < 4 ? kk : 508 + (kk - 4);
                float b = sb1[sig * 8 + m];
                float2 acc = splat(b);
                const float* w1p = sw1 + sig * 224 + m * 28;
                #pragma unroll
                for (int c = 0; c < 4; c++)
                    #pragma unroll
                    for (int j1 = 0; j1 < 7; j1++)
                        acc = ffma2(splat(w1p[c * 7 + j1]), D[sidx(c, q - 3 + j1)], acc);
                He[k] = acc;
            } else if (i < 292) {
                // Weff34[c][t] = sum_m sum_j4 w4[m][j4] * w3[m][c][t-2*j4]
                int k = i - 240, c = k / 13, t = k % 13;
                float s = 0.f;
                #pragma unroll
                for (int m = 0; m < 2; m++)
                    #pragma unroll
                    for (int j4 = 0; j4 < 5; j4++) {
                        int j3 = t - 2 * j4;
                        if (j3 >= 0 && j3 <= 4)
                            s += sw4[sig * 10 + m * 5 + j4] * sw3[sig * 40 + m * 20 + c * 5 + j3];
                    }
                W[344 + k] = s;
            } else if (i < 296) {
                int o = i - 292;
                float s = sb2[sig * 4 + o];
                #pragma unroll
                for (int m = 0; m < 8; m++) {
                    float swm = 0.f;
                    #pragma unroll
                    for (int j2 = 0; j2 < 5; j2++) swm += sw2[sig * 160 + o * 40 + m * 5 + j2];
                    s += swm * sb1[sig * 8 + m];
                }
                W[176 + o] = s;
            } else if (i == 296) {
                float s = sb4[sig];
                #pragma unroll
                for (int m = 0; m < 2; m++) {
                    float swm = 0.f;
                    #pragma unroll
                    for (int j4 = 0; j4 < 5; j4++) swm += sw4[sig * 10 + m * 5 + j4];
                    s += swm * sb3[sig * 2 + m];
                }
                W[396] = s;
            } else if (i < 461) {
                int k = i - 297;   // 0..163
                W[180 + k] = (k < 160) ? sw2[sig * 160 + k] : sb2[sig * 4 + (k - 160)];
            } else if (i < 501) {
                W[397 + (i - 461)] = sw3[sig * 40 + (i - 461)];
            } else if (i < 503) {
                W[437 + (i - 501)] = sb3[sig * 2 + (i - 501)];
            } else if (i < 513) {
                W[439 + (i - 503)] = sw4[sig * 10 + (i - 503)];
            } else {
                W[449] = sb4[sig];
            }
        }
        __syncthreads();

        const float* W12 = W,       * BE12 = W + 176;
        const float* W2R = W + 180, * B2R  = W + 340;
        const float* W34 = W + 344;
        const float  BE34 = W[396];
        const float* W4R = W + 439;

        // ---- fused L12: 4->4 k11 composed conv + SELU -> H2 ----
        if (tid != 0 && tid != 127) {
            float2 acc[4][4];   // [o][r]
            #pragma unroll
            for (int o = 0; o < 4; o++) {
                float2 b = splat(BE12[o]);
                #pragma unroll
                for (int r = 0; r < 4; r++) acc[o][r] = b;
            }
            #pragma unroll
            for (int c = 0; c < 4; c++) {
                float2 in[14];
                #pragma unroll
                for (int t = 0; t < 14; t++) in[t] = D[sidx(c, base - 5 + t)];
                #pragma unroll
                for (int o = 0; o < 4; o++)
                    #pragma unroll
                    for (int t = 0; t < 11; t++) {
                        float2 wv = splat(W12[o * 44 + c * 11 + t]);
                        #pragma unroll
                        for (int r = 0; r < 4; r++)
                            acc[o][r] = ffma2(wv, in[r + t], acc[o][r]);
                    }
            }
            #pragma unroll
            for (int o = 0; o < 4; o++)
                #pragma unroll
                for (int r = 0; r < 4; r++)
                    H2[sidx(o, base + r)] = selu2(acc[o][r]);
        } else {
            const int left = (tid == 0);
            // explicit (reflected-H1) positions: left p={0,1}, right p={510,511}
            #pragma unroll
            for (int e = 0; e < 2; e++) {
                int p = left ? e : 510 + e;
                #pragma unroll
                for (int o = 0; o < 4; o++) {
                    float2 a = splat(B2R[o]);
                    #pragma unroll
                    for (int m = 0; m < 8; m++)
                        #pragma unroll
                        for (int j2 = 0; j2 < 5; j2++) {
                            int q = refl(p - 2 + j2);
                            int k = q < 8 ? q : q - 504;
                            a = ffma2(splat(W2R[o * 40 + m * 5 + j2]), He[m * 8 + k], a);
                        }
                    H2[sidx(o, p)] = selu2(a);
                }
            }
            // composed positions: left p={2,3}, right p={508,509}
            #pragma unroll
            for (int e = 0; e < 2; e++) {
                int p = left ? 2 + e : 508 + e;
                float2 a[4];
                #pragma unroll
                for (int o = 0; o < 4; o++) a[o] = splat(BE12[o]);
                #pragma unroll
                for (int c = 0; c < 4; c++)
                    #pragma unroll
                    for (int t = 0; t < 11; t++) {
                        float2 dv = D[sidx(c, p - 5 + t)];
                        #pragma unroll
                        for (int o = 0; o < 4; o++)
                            a[o] = ffma2(splat(W12[o * 44 + c * 11 + t]), dv, a[o]);
                    }
                #pragma unroll
                for (int o = 0; o < 4; o++) H2[sidx(o, p)] = selu2(a[o]);
            }
        }
        __syncthreads();
        fill_halo(H2, 4, tid);
        __syncthreads();

        // ---- H3 edge values (needs H2 + halo) ----
        if (tid < 32) {
            int m = tid >> 4, kk = tid & 15;
            int q = kk < 8 ? kk : 504 + (kk - 8);
            float2 a = splat(W[437 + m]);   // b3[m]
            #pragma unroll
            for (int c = 0; c < 4; c++)
                #pragma unroll
                for (int j3 = 0; j3 < 5; j3++)
                    a = ffma2(splat(W[397 + m * 20 + c * 5 + j3]), H2[sidx(c, q - 2 + j3)], a);
            H3e[m * 16 + kk] = a;
        }
        __syncthreads();

        // ---- fused L34: 4->1 k13 composed conv + SELU -> out ----
        float2 res[4];
        if (tid != 0 && tid != 127) {
            float2 acc[4];
            #pragma unroll
            for (int r = 0; r < 4; r++) acc[r] = splat(BE34);
            #pragma unroll
            for (int c = 0; c < 4; c++) {
                float2 in[16];
                #pragma unroll
                for (int t = 0; t < 16; t++) in[t] = H2[sidx(c, base - 6 + t)];
                #pragma unroll
                for (int t = 0; t < 13; t++) {
                    float2 wv = splat(W34[c * 13 + t]);
                    #pragma unroll
                    for (int r = 0; r < 4; r++)
                        acc[r] = ffma2(wv, in[r + t], acc[r]);
                }
            }
            #pragma unroll
            for (int r = 0; r < 4; r++) res[r] = selu2(acc[r]);
        } else {
            const float b4 = W[449];
            #pragma unroll
            for (int r = 0; r < 4; r++) {
                int p = base + r;
                float2 a = splat(b4);
                #pragma unroll
                for (int m = 0; m < 2; m++)
                    #pragma unroll
                    for (int j4 = 0; j4 < 5; j4++) {
                        int q = refl(p - 4 + 2 * j4);
                        int k = q < 8 ? q : 8 + (q - 504);
                        a = ffma2(splat(W4R[m * 5 + j4]), H3e[m * 16 + k], a);
                    }
                res[r] = selu2(a);
            }
        }

        const size_t o0 = ((size_t)(2 * bp)     * 50 + sig) * NPOS + base;
        const size_t o1 = ((size_t)(2 * bp + 1) * 50 + sig) * NPOS + base;
        *reinterpret_cast<float4*>(out + o0) =
            make_float4(res[0].x, res[1].x, res[2].x, res[3].x);
        *reinterpret_cast<float4*>(out + o1) =
            make_float4(res[0].y, res[1].y, res[2].y, res[3].y);
    }
}

// ---------------------------------------------------------------------------
// launch
// ---------------------------------------------------------------------------

static const int SMEM_PREP = (16 * CST) * (int)sizeof(float2) + 336 * 4 + 64 * (int)sizeof(float2);
static const int SMEM_SIG  = (8 * CST + 96) * (int)sizeof(float2) + 452 * 4;

extern "C" void kernel_launch(void* const* d_in, const int* in_sizes, int n_in,
                              void* d_out, int out_size) {
    const float* lat = (const float*)d_in[0];
    const float* shw1 = (const float*)d_in[1];
    const float* shb1 = (const float*)d_in[2];
    const float* shw2 = (const float*)d_in[3];
    const float* shb2 = (const float*)d_in[4];
    const float* lng  = (const float*)d_in[5];
    const float* lnb  = (const float*)d_in[6];
    const float* sgw1 = (const float*)d_in[7];
    const float* sgb1 = (const float*)d_in[8];
    const float* sgw2 = (const float*)d_in[9];
    const float* sgb2 = (const float*)d_in[10];
    const float* sgw3 = (const float*)d_in[11];
    const float* sgb3 = (const float*)d_in[12];
    const float* sgw4 = (const float*)d_in[13];
    const float* sgb4 = (const float*)d_in[14];
    float* out = (float*)d_out;

    cudaFuncSetAttribute(prep_kernel, cudaFuncAttributeMaxDynamicSharedMemorySize, SMEM_PREP);
    cudaFuncSetAttribute(sig_kernel,  cudaFuncAttributeMaxDynamicSharedMemorySize, SMEM_SIG);

    prep_kernel<<<NBP, 512, SMEM_PREP>>>(lat, shw1, shb1, shw2, shb2, lng, lnb);
    sig_kernel<<<dim3(NBP, 25), 128, SMEM_SIG>>>(sgw1, sgb1, sgw2, sgb2,
                                                 sgw3, sgb3, sgw4, sgb4, out);
}